// round 5
// baseline (speedup 1.0000x reference)
#include <cuda_runtime.h>
#include <cstdint>

// Problem constants
#define NUM_USERS 100000
#define NUM_ITEMS 100000
#define EMB_K 6
#define BATCH 2048

#define N4      (NUM_USERS / 4)   // 25000 16B-vectors per row
#define ROWS    8                 // batch rows per block (split 4+4 across thread groups)
#define RPT     4                 // rows per thread
#define NSPLIT  2                 // column splits
#define THREADS 256
#define GTHREADS 128              // threads per row-group
#define ROWGROUPS (BATCH / ROWS)          // 256
#define GRID      (ROWGROUPS * NSPLIT)    // 512
#define COLS4     (N4 / NSPLIT)           // 12500 16B-vectors per split

typedef unsigned long long u64;

// Packed fp32x2 FMA (sm_100+; SASS FFMA2 — 2 FMAs per issue slot)
__device__ __forceinline__ u64 fma2(u64 a, u64 b, u64 c) {
    u64 d;
    asm("fma.rn.f32x2 %0, %1, %2, %3;" : "=l"(d) : "l"(a), "l"(b), "l"(c));
    return d;
}
__device__ __forceinline__ float pair_sum(u64 v) {
    const float lo = __uint_as_float((unsigned int)(v & 0xffffffffull));
    const float hi = __uint_as_float((unsigned int)(v >> 32));
    return lo + hi;
}

// Scratch: partial U_emb per split, and completion counter
__device__ float g_Upart[NSPLIT][BATCH][EMB_K];
__device__ unsigned int g_counter;

__global__ __launch_bounds__(THREADS, 2)   // cap regs at 128 -> 2 blocks/SM
void fused_kernel(const ulonglong2* __restrict__ x_user2,
                  const ulonglong2* __restrict__ Ww2,
                  const void*  __restrict__ x_item,
                  const float* __restrict__ H_w,
                  const float* __restrict__ W1, const float* __restrict__ b1,
                  const float* __restrict__ W2, const float* __restrict__ b2,
                  const float* __restrict__ W3,
                  float* __restrict__ out) {
    const int tid   = threadIdx.x;
    const int bx    = blockIdx.x;
    const int split = bx & (NSPLIT - 1);
    const int rg    = bx >> 1;              // log2(NSPLIT)
    const int group = tid >> 7;             // 0 or 1
    const int gtid  = tid & (GTHREADS - 1);
    const int row0  = rg * ROWS + group * RPT;
    const int c0    = split * COLS4;
    const int c1    = c0 + COLS4;

    // Per-row pointers; W strides by N4 per k.
    const ulonglong2* xp0 = x_user2 + (size_t)(row0 + 0) * N4 + c0 + gtid;
    const ulonglong2* xp1 = x_user2 + (size_t)(row0 + 1) * N4 + c0 + gtid;
    const ulonglong2* xp2 = x_user2 + (size_t)(row0 + 2) * N4 + c0 + gtid;
    const ulonglong2* xp3 = x_user2 + (size_t)(row0 + 3) * N4 + c0 + gtid;
    const ulonglong2* wp  = Ww2 + c0 + gtid;

    u64 acc[RPT][EMB_K];
#pragma unroll
    for (int r = 0; r < RPT; r++)
#pragma unroll
        for (int k = 0; k < EMB_K; k++)
            acc[r][k] = 0ull;   // (0.0f, 0.0f)

    for (int i4 = c0 + gtid; i4 < c1; i4 += GTHREADS) {
        ulonglong2 w[EMB_K];
#pragma unroll
        for (int k = 0; k < EMB_K; k++)
            w[k] = __ldg(wp + (size_t)k * N4);

        const ulonglong2 x0 = __ldg(xp0);
        const ulonglong2 x1 = __ldg(xp1);
        const ulonglong2 x2 = __ldg(xp2);
        const ulonglong2 x3 = __ldg(xp3);

#pragma unroll
        for (int k = 0; k < EMB_K; k++) {
            acc[0][k] = fma2(x0.x, w[k].x, acc[0][k]);
            acc[0][k] = fma2(x0.y, w[k].y, acc[0][k]);
            acc[1][k] = fma2(x1.x, w[k].x, acc[1][k]);
            acc[1][k] = fma2(x1.y, w[k].y, acc[1][k]);
            acc[2][k] = fma2(x2.x, w[k].x, acc[2][k]);
            acc[2][k] = fma2(x2.y, w[k].y, acc[2][k]);
            acc[3][k] = fma2(x3.x, w[k].x, acc[3][k]);
            acc[3][k] = fma2(x3.y, w[k].y, acc[3][k]);
        }

        xp0 += GTHREADS; xp1 += GTHREADS; xp2 += GTHREADS; xp3 += GTHREADS;
        wp  += GTHREADS;
    }

    // ---------------- block reduction -> partial U_emb ----------------
    // Warps 0-3 hold rows row0_g0+0..3; warps 4-7 hold rows row0_g1+0..3.
    __shared__ float sred[THREADS / 32][RPT * EMB_K];   // 8 x 24 floats
    const int lane = tid & 31;
    const int warp = tid >> 5;

#pragma unroll
    for (int r = 0; r < RPT; r++) {
#pragma unroll
        for (int k = 0; k < EMB_K; k++) {
            float v = pair_sum(acc[r][k]);
#pragma unroll
            for (int off = 16; off > 0; off >>= 1)
                v += __shfl_down_sync(0xffffffffu, v, off);
            if (lane == 0) sred[warp][r * EMB_K + k] = v;
        }
    }
    __syncthreads();

    if (tid < ROWS * EMB_K) {                 // 48 threads
        const int rglob = tid / EMB_K;        // 0..7
        const int k     = tid % EMB_K;
        const int wbase = (rglob < RPT) ? 0 : 4;
        const int lidx  = (rglob & (RPT - 1)) * EMB_K + k;
        float s = 0.0f;
#pragma unroll
        for (int w2 = 0; w2 < 4; w2++)
            s += sred[wbase + w2][lidx];
        g_Upart[split][rg * ROWS + rglob][k] = s;
    }

    // ---------------- last-block election ----------------
    __shared__ int s_last;
    __threadfence();                 // publish partials
    __syncthreads();
    if (tid == 0) {
        unsigned int old = atomicAdd(&g_counter, 1u);
        s_last = (old == GRID - 1) ? 1 : 0;
    }
    __syncthreads();
    if (!s_last) return;

    // We are the last block: all partials are visible.
    if (tid == 0) g_counter = 0;     // reset for next graph replay
    __threadfence();

    // ---------------- int64/int32 index detection ----------------
    __shared__ int s_nz;
    if (tid == 0) s_nz = 0;
    __syncthreads();
    {
        const unsigned int* p = (const unsigned int*)x_item;
        for (int b = tid; b < 1024; b += THREADS)
            if (p[2 * b + 1] != 0u) s_nz = 1;   // benign race
    }

    // ---------------- tiny MLP weights into smem ----------------
    __shared__ float sW1[16 * 12], sb1[16], sW2[8 * 16], sb2[8], sW3[9];
    if (tid < 16 * 12) sW1[tid] = W1[tid];
    if (tid < 16)      sb1[tid] = b1[tid];
    if (tid < 8 * 16)  sW2[tid] = W2[tid];
    if (tid < 8)       sb2[tid] = b2[tid];
    if (tid < 9)       sW3[tid] = W3[tid];
    __syncthreads();
    const bool is64 = (s_nz == 0);

    // ---------------- gather + MLP for all BATCH elements ----------------
    for (int b = tid; b < BATCH; b += THREADS) {
        long long idx;
        if (is64) idx = ((const long long*)x_item)[b];
        else      idx = (long long)(((const int*)x_item)[b]);

        float z[12];
#pragma unroll
        for (int k = 0; k < EMB_K; k++) {
            float s = 0.0f;
#pragma unroll
            for (int sp = 0; sp < NSPLIT; sp++)
                s += g_Upart[sp][b][k];
            z[k] = s;
        }
#pragma unroll
        for (int k = 0; k < EMB_K; k++)
            z[EMB_K + k] = __ldg(&H_w[(size_t)k * NUM_ITEMS + idx]);

        float h1[16];
#pragma unroll
        for (int j = 0; j < 16; j++) {
            float s = sb1[j];
#pragma unroll
            for (int i = 0; i < 12; i++)
                s = fmaf(z[i], sW1[j * 12 + i], s);
            h1[j] = fmaxf(s, 0.0f);
        }

        float h2[8];
#pragma unroll
        for (int j = 0; j < 8; j++) {
            float s = sb2[j];
#pragma unroll
            for (int i = 0; i < 16; i++)
                s = fmaf(h1[i], sW2[j * 16 + i], s);
            h2[j] = fmaxf(s, 0.0f);
        }

        float o = sW3[8];   // ones-column term
#pragma unroll
        for (int i = 0; i < 8; i++)
            o = fmaf(h2[i], sW3[i], o);

        out[b] = o;
    }
}

extern "C" void kernel_launch(void* const* d_in, const int* in_sizes, int n_in,
                              void* d_out, int out_size) {
    const float* x_user = (const float*)d_in[0];
    const void*  x_item = d_in[1];
    const float* W_w    = (const float*)d_in[2];
    const float* H_w    = (const float*)d_in[3];
    const float* W1     = (const float*)d_in[4];
    const float* b1     = (const float*)d_in[5];
    const float* W2     = (const float*)d_in[6];
    const float* b2     = (const float*)d_in[7];
    const float* W3     = (const float*)d_in[8];
    float* out          = (float*)d_out;

    fused_kernel<<<GRID, THREADS>>>(
        (const ulonglong2*)x_user, (const ulonglong2*)W_w, x_item, H_w,
        W1, b1, W2, b2, W3, out);
}

// round 6
// speedup vs baseline: 1.0212x; 1.0212x over previous
#include <cuda_runtime.h>
#include <cstdint>

// Problem constants
#define NUM_USERS 100000
#define NUM_ITEMS 100000
#define EMB_K 6
#define BATCH 2048

#define N4      (NUM_USERS / 4)   // 25000 float4 per row
#define ROWS    32                // batch rows per block
#define RPW     4                 // rows per warp (8 warps)
#define NSPLIT  10                // column splits
#define THREADS 256
#define CSPLIT  (N4 / NSPLIT)     // 2500 float4 per split
#define ROWGROUPS (BATCH / ROWS)          // 64
#define GRID      (ROWGROUPS * NSPLIT)    // 640

// Scratch: partial U_emb per split, and completion counter
__device__ float g_Upart[NSPLIT][BATCH][EMB_K];
__device__ unsigned int g_counter;

__global__ __launch_bounds__(THREADS, 3)   // cap regs ~85 -> 3 blocks/SM, 24 warps
void fused_kernel(const float4* __restrict__ x_user4,
                  const float4* __restrict__ Ww4,
                  const void*  __restrict__ x_item,
                  const float* __restrict__ H_w,
                  const float* __restrict__ W1, const float* __restrict__ b1,
                  const float* __restrict__ W2, const float* __restrict__ b2,
                  const float* __restrict__ W3,
                  float* __restrict__ out) {
    const int tid   = threadIdx.x;
    const int lane  = tid & 31;
    const int warp  = tid >> 5;
    const int bx    = blockIdx.x;
    const int split = bx % NSPLIT;
    const int rg    = bx / NSPLIT;
    const int row0  = rg * ROWS + warp * RPW;   // this warp's 4 rows
    const int c0    = split * CSPLIT;
    const int c1    = c0 + CSPLIT;

    // All 8 warps sweep the SAME columns (c0+lane, +32, ...) so W stays hot in L1.
    const float4* wp  = Ww4 + c0 + lane;                       // k strides by N4
    const float4* xp0 = x_user4 + (size_t)(row0 + 0) * N4 + c0 + lane;
    const float4* xp1 = x_user4 + (size_t)(row0 + 1) * N4 + c0 + lane;
    const float4* xp2 = x_user4 + (size_t)(row0 + 2) * N4 + c0 + lane;
    const float4* xp3 = x_user4 + (size_t)(row0 + 3) * N4 + c0 + lane;

    float acc[RPW][EMB_K];
#pragma unroll
    for (int r = 0; r < RPW; r++)
#pragma unroll
        for (int k = 0; k < EMB_K; k++)
            acc[r][k] = 0.0f;

    for (int col = c0 + lane; col < c1; col += 32) {
        float4 w[EMB_K];
#pragma unroll
        for (int k = 0; k < EMB_K; k++)
            w[k] = __ldg(wp + (size_t)k * N4);     // L1-cached: warps share

        const float4 x0 = __ldcs(xp0);             // streaming: evict-first
        const float4 x1 = __ldcs(xp1);
        const float4 x2 = __ldcs(xp2);
        const float4 x3 = __ldcs(xp3);

#pragma unroll
        for (int k = 0; k < EMB_K; k++) {
            acc[0][k] = fmaf(x0.x, w[k].x, acc[0][k]);
            acc[0][k] = fmaf(x0.y, w[k].y, acc[0][k]);
            acc[0][k] = fmaf(x0.z, w[k].z, acc[0][k]);
            acc[0][k] = fmaf(x0.w, w[k].w, acc[0][k]);
            acc[1][k] = fmaf(x1.x, w[k].x, acc[1][k]);
            acc[1][k] = fmaf(x1.y, w[k].y, acc[1][k]);
            acc[1][k] = fmaf(x1.z, w[k].z, acc[1][k]);
            acc[1][k] = fmaf(x1.w, w[k].w, acc[1][k]);
            acc[2][k] = fmaf(x2.x, w[k].x, acc[2][k]);
            acc[2][k] = fmaf(x2.y, w[k].y, acc[2][k]);
            acc[2][k] = fmaf(x2.z, w[k].z, acc[2][k]);
            acc[2][k] = fmaf(x2.w, w[k].w, acc[2][k]);
            acc[3][k] = fmaf(x3.x, w[k].x, acc[3][k]);
            acc[3][k] = fmaf(x3.y, w[k].y, acc[3][k]);
            acc[3][k] = fmaf(x3.z, w[k].z, acc[3][k]);
            acc[3][k] = fmaf(x3.w, w[k].w, acc[3][k]);
        }

        wp  += 32;
        xp0 += 32; xp1 += 32; xp2 += 32; xp3 += 32;
    }

    // ---------------- intra-warp reduction -> partial U_emb ----------------
    // Each warp's rows are complete after its sweep: no cross-warp reduction.
#pragma unroll
    for (int r = 0; r < RPW; r++) {
#pragma unroll
        for (int k = 0; k < EMB_K; k++) {
            float v = acc[r][k];
#pragma unroll
            for (int off = 16; off > 0; off >>= 1)
                v += __shfl_down_sync(0xffffffffu, v, off);
            if (lane == 0)
                g_Upart[split][row0 + r][k] = v;
        }
    }

    // ---------------- last-block election ----------------
    __shared__ int s_last;
    __threadfence();                 // publish partials
    __syncthreads();
    if (tid == 0) {
        unsigned int old = atomicAdd(&g_counter, 1u);
        s_last = (old == GRID - 1) ? 1 : 0;
    }
    __syncthreads();
    if (!s_last) return;

    // We are the last block: all partials are visible.
    if (tid == 0) g_counter = 0;     // reset for next graph replay
    __threadfence();

    // ---------------- int64/int32 index detection ----------------
    __shared__ int s_nz;
    if (tid == 0) s_nz = 0;
    __syncthreads();
    {
        const unsigned int* p = (const unsigned int*)x_item;
        for (int b = tid; b < 1024; b += THREADS)
            if (p[2 * b + 1] != 0u) s_nz = 1;   // benign race
    }

    // ---------------- tiny MLP weights into smem ----------------
    __shared__ float sW1[16 * 12], sb1[16], sW2[8 * 16], sb2[8], sW3[9];
    if (tid < 16 * 12) sW1[tid] = W1[tid];
    if (tid < 16)      sb1[tid] = b1[tid];
    if (tid < 8 * 16)  sW2[tid] = W2[tid];
    if (tid < 8)       sb2[tid] = b2[tid];
    if (tid < 9)       sW3[tid] = W3[tid];
    __syncthreads();
    const bool is64 = (s_nz == 0);

    // ---------------- gather + MLP for all BATCH elements ----------------
    for (int b = tid; b < BATCH; b += THREADS) {
        long long idx;
        if (is64) idx = ((const long long*)x_item)[b];
        else      idx = (long long)(((const int*)x_item)[b]);

        float z[12];
#pragma unroll
        for (int k = 0; k < EMB_K; k++) {
            float s = 0.0f;
#pragma unroll
            for (int sp = 0; sp < NSPLIT; sp++)
                s += g_Upart[sp][b][k];
            z[k] = s;
        }
#pragma unroll
        for (int k = 0; k < EMB_K; k++)
            z[EMB_K + k] = __ldg(&H_w[(size_t)k * NUM_ITEMS + idx]);

        float h1[16];
#pragma unroll
        for (int j = 0; j < 16; j++) {
            float s = sb1[j];
#pragma unroll
            for (int i = 0; i < 12; i++)
                s = fmaf(z[i], sW1[j * 12 + i], s);
            h1[j] = fmaxf(s, 0.0f);
        }

        float h2[8];
#pragma unroll
        for (int j = 0; j < 8; j++) {
            float s = sb2[j];
#pragma unroll
            for (int i = 0; i < 16; i++)
                s = fmaf(h1[i], sW2[j * 16 + i], s);
            h2[j] = fmaxf(s, 0.0f);
        }

        float o = sW3[8];   // ones-column term
#pragma unroll
        for (int i = 0; i < 8; i++)
            o = fmaf(h2[i], sW3[i], o);

        out[b] = o;
    }
}

extern "C" void kernel_launch(void* const* d_in, const int* in_sizes, int n_in,
                              void* d_out, int out_size) {
    const float* x_user = (const float*)d_in[0];
    const void*  x_item = d_in[1];
    const float* W_w    = (const float*)d_in[2];
    const float* H_w    = (const float*)d_in[3];
    const float* W1     = (const float*)d_in[4];
    const float* b1     = (const float*)d_in[5];
    const float* W2     = (const float*)d_in[6];
    const float* b2     = (const float*)d_in[7];
    const float* W3     = (const float*)d_in[8];
    float* out          = (float*)d_out;

    fused_kernel<<<GRID, THREADS>>>(
        (const float4*)x_user, (const float4*)W_w, x_item, H_w,
        W1, b1, W2, b2, W3, out);
}